// round 3
// baseline (speedup 1.0000x reference)
#include <cuda_runtime.h>
#include <math.h>
#include <stdint.h>

// VQ-VAE forward: enc(2x GEMM+ReLU) -> VQ (fused dist+argmin+gather) -> dec(2x GEMM)
// All inner loops use packed fp32x2 FMA (fma.rn.f32x2 -> SASS FFMA2), which is
// bit-identical to scalar FFMA but 2x rate. Shapes: N=16384, IN=1024, ENC=256, K=8192
#define NT   16384
#define DIN  1024
#define DE   256
#define KC   8192

typedef unsigned long long u64;

// Scratch (static __device__ arrays: allocation-free per harness rules)
static __device__ float g_h  [(size_t)NT * DE];   // 16 MB
static __device__ float g_enc[(size_t)NT * DE];   // 16 MB
static __device__ float g_g  [(size_t)NT * DE];   // 16 MB
static __device__ float g_x2 [NT];
static __device__ float g_c2 [KC];

// ---- packed f32x2 helpers (sm_100a) ---------------------------------------
__device__ __forceinline__ void ffma2(u64 &d, u64 a, u64 b) {
    // d.lanes = a.lanes * b.lanes + d.lanes  (two fp32 RN fmas)
    asm("fma.rn.f32x2 %0, %1, %2, %0;" : "+l"(d) : "l"(a), "l"(b));
}
__device__ __forceinline__ u64 dup2(float x) {
    u64 r; asm("mov.b64 %0, {%1, %1};" : "=l"(r) : "f"(x)); return r;
}
__device__ __forceinline__ void unpack2(u64 v, float &x, float &y) {
    asm("mov.b64 {%0, %1}, %2;" : "=f"(x), "=f"(y) : "l"(v));
}

// ---------------------------------------------------------------------------
// Tiled fp32 SGEMM (FFMA2 inner loop):
// C[M,Nn] = (opt ReLU)(A[M,Kk] @ B[Kk,Nn] + bias[Nn])
// BM=BN=128, BK=16, 256 threads, 8x8 per thread.
// A smem tile stored lane-duplicated (8B per element) so the packed-FMA 'a'
// operand loads directly as LDS.64 with no per-iteration packing movs.
// ---------------------------------------------------------------------------
template<bool RELU>
__global__ __launch_bounds__(256)
void sgemm_bias(const float* __restrict__ A, const float* __restrict__ B,
                const float* __restrict__ bias, float* __restrict__ C,
                int M, int Nn, int Kk)
{
    const int BM = 128, BN = 128, BK = 16;
    __shared__ u64  As2[BK][BM];               // duplicated-pair A tile (16 KB)
    __shared__ __align__(16) float Bs[BK][BN]; // B tile (8 KB)

    const int tid = threadIdx.x;
    const int tm  = tid >> 4;    // 0..15 (row group)
    const int tn  = tid & 15;    // 0..15 (col group)
    const int bm  = blockIdx.y * BM;
    const int bn  = blockIdx.x * BN;

    u64 acc2[8][4];
#pragma unroll
    for (int i = 0; i < 8; i++)
#pragma unroll
        for (int j = 0; j < 4; j++) acc2[i][j] = 0ull;

    for (int k0 = 0; k0 < Kk; k0 += BK) {
        // A tile: 128 rows x 16 k, transposed + duplicated: As2[k][m] = (a,a)
#pragma unroll
        for (int i = 0; i < 2; i++) {
            int lin = tid + i * 256;          // float4 index, 0..511
            int row = lin >> 2;               // 4 float4 per row
            int kq  = lin & 3;
            float4 v = *(const float4*)(A + (size_t)(bm + row) * Kk + k0 + kq * 4);
            As2[kq * 4 + 0][row] = dup2(v.x);
            As2[kq * 4 + 1][row] = dup2(v.y);
            As2[kq * 4 + 2][row] = dup2(v.z);
            As2[kq * 4 + 3][row] = dup2(v.w);
        }
        // B tile: 16 k-rows x 128 n, row-major -> Bs[k][n]
#pragma unroll
        for (int i = 0; i < 2; i++) {
            int lin = tid + i * 256;
            int kr  = lin >> 5;               // 32 float4 per k-row
            int nq  = lin & 31;
            *(float4*)&Bs[kr][nq * 4] =
                *(const float4*)(B + (size_t)(k0 + kr) * Nn + bn + nq * 4);
        }
        __syncthreads();

#pragma unroll
        for (int k = 0; k < BK; k++) {
            u64 a2[8], b2[4];
            const u64* bp = (const u64*)&Bs[k][tn * 8];
#pragma unroll
            for (int j = 0; j < 4; j++) b2[j] = bp[j];
#pragma unroll
            for (int i = 0; i < 8; i++) a2[i] = As2[k][tm * 8 + i];
#pragma unroll
            for (int i = 0; i < 8; i++)
#pragma unroll
                for (int j = 0; j < 4; j++) ffma2(acc2[i][j], a2[i], b2[j]);
        }
        __syncthreads();
    }

#pragma unroll
    for (int i = 0; i < 8; i++) {
        int row = bm + tm * 8 + i;
        int col = bn + tn * 8;
        float r[8];
#pragma unroll
        for (int j = 0; j < 4; j++) unpack2(acc2[i][j], r[2 * j], r[2 * j + 1]);
#pragma unroll
        for (int j = 0; j < 8; j++) {
            r[j] += bias[col + j];
            if (RELU) r[j] = fmaxf(r[j], 0.f);
        }
        *(float4*)(C + (size_t)row * Nn + col)     = make_float4(r[0], r[1], r[2], r[3]);
        *(float4*)(C + (size_t)row * Nn + col + 4) = make_float4(r[4], r[5], r[6], r[7]);
    }
}

// ---------------------------------------------------------------------------
// Row squared norms: out[row] = sum(X[row,:]^2). blockDim=(32,8), 1 warp/row.
// ---------------------------------------------------------------------------
__global__ void row_sqnorm(const float* __restrict__ X, float* __restrict__ out,
                           int ncols)
{
    int row = blockIdx.x * 8 + threadIdx.y;
    float s = 0.f;
    for (int c = threadIdx.x * 4; c < ncols; c += 128) {
        float4 v = *(const float4*)(X + (size_t)row * ncols + c);
        s += v.x * v.x + v.y * v.y + v.z * v.z + v.w * v.w;
    }
#pragma unroll
    for (int o = 16; o > 0; o >>= 1) s += __shfl_xor_sync(0xFFFFFFFFu, s, o);
    if (threadIdx.x == 0) out[row] = s;
}

// ---------------------------------------------------------------------------
// Fused VQ: for 128 encoded rows, stream over all 8192 codewords computing
// m = c2[j] - 2*dot(enc_row, cw_j)  (x2 is a per-row constant -> argmin safe),
// running (min, first-idx), final dist = sqrt(max(x2 + m, 0)), gather rows.
// Inner loop identical FFMA2 structure as sgemm (bit-identical to fp32).
// ---------------------------------------------------------------------------
__global__ __launch_bounds__(256)
void vq_kernel(const float* __restrict__ enc, const float* __restrict__ cw,
               const float* __restrict__ c2,  const float* __restrict__ x2,
               float* __restrict__ out_idx, float* __restrict__ out_dist,
               float* __restrict__ out_quant)
{
    const int BM = 128, BN = 128, BK = 16;
    __shared__ u64  As2[BK][BM];               // duplicated encoded tile (16 KB)
    __shared__ __align__(16) float Bs[BK][BN]; // codeword tile (8 KB)
    __shared__ float smin[128][16];
    __shared__ int   sidx[128][16];
    __shared__ int   widx[128];

    const int tid = threadIdx.x;
    const int tm  = tid >> 4;
    const int tn  = tid & 15;
    const int bm  = blockIdx.x * BM;

    float rmin[8];
    int   ridx[8];
#pragma unroll
    for (int i = 0; i < 8; i++) { rmin[i] = 3.4e38f; ridx[i] = 0; }

    for (int c0 = 0; c0 < KC; c0 += BN) {
        u64 acc2[8][4];
#pragma unroll
        for (int i = 0; i < 8; i++)
#pragma unroll
            for (int j = 0; j < 4; j++) acc2[i][j] = 0ull;

        for (int k0 = 0; k0 < DE; k0 += BK) {
            // encoded tile (rows bm..bm+127), transposed+duplicated into As2[k][m]
#pragma unroll
            for (int i = 0; i < 2; i++) {
                int lin = tid + i * 256;
                int row = lin >> 2;
                int kq  = lin & 3;
                float4 v = *(const float4*)(enc + (size_t)(bm + row) * DE + k0 + kq * 4);
                As2[kq * 4 + 0][row] = dup2(v.x);
                As2[kq * 4 + 1][row] = dup2(v.y);
                As2[kq * 4 + 2][row] = dup2(v.z);
                As2[kq * 4 + 3][row] = dup2(v.w);
            }
            // codeword tile (rows c0..c0+127), transposed into Bs[k][j]
#pragma unroll
            for (int i = 0; i < 2; i++) {
                int lin = tid + i * 256;
                int j   = lin >> 2;
                int kq  = lin & 3;
                float4 v = *(const float4*)(cw + (size_t)(c0 + j) * DE + k0 + kq * 4);
                Bs[kq * 4 + 0][j] = v.x;
                Bs[kq * 4 + 1][j] = v.y;
                Bs[kq * 4 + 2][j] = v.z;
                Bs[kq * 4 + 3][j] = v.w;
            }
            __syncthreads();

#pragma unroll
            for (int k = 0; k < BK; k++) {
                u64 a2[8], b2[4];
                const u64* bp = (const u64*)&Bs[k][tn * 8];
#pragma unroll
                for (int j = 0; j < 4; j++) b2[j] = bp[j];
#pragma unroll
                for (int i = 0; i < 8; i++) a2[i] = As2[k][tm * 8 + i];
#pragma unroll
                for (int i = 0; i < 8; i++)
#pragma unroll
                    for (int j = 0; j < 4; j++) ffma2(acc2[i][j], a2[i], b2[j]);
            }
            __syncthreads();
        }

        float cc[8];
#pragma unroll
        for (int j = 0; j < 8; j++) cc[j] = c2[c0 + tn * 8 + j];
#pragma unroll
        for (int i = 0; i < 8; i++) {
            float dv[8];
#pragma unroll
            for (int j = 0; j < 4; j++) unpack2(acc2[i][j], dv[2 * j], dv[2 * j + 1]);
#pragma unroll
            for (int j = 0; j < 8; j++) {
                float d = cc[j] - 2.f * dv[j];
                int col = c0 + tn * 8 + j;   // ascending within thread & across chunks
                if (d < rmin[i]) { rmin[i] = d; ridx[i] = col; }
            }
        }
    }

    // reduce across the 16 column-group threads per row (preserve first-min)
#pragma unroll
    for (int i = 0; i < 8; i++) {
        smin[tm * 8 + i][tn] = rmin[i];
        sidx[tm * 8 + i][tn] = ridx[i];
    }
    __syncthreads();

    if (tid < 128) {
        float m = smin[tid][0];
        int   id = sidx[tid][0];
#pragma unroll
        for (int t = 1; t < 16; t++) {
            float v = smin[tid][t];
            int   w = sidx[tid][t];
            if (v < m || (v == m && w < id)) { m = v; id = w; }
        }
        float d2 = x2[bm + tid] + m;
        out_dist[bm + tid] = sqrtf(fmaxf(d2, 0.f));
        out_idx [bm + tid] = (float)id;
        widx[tid] = id;
    }
    __syncthreads();

    // gather quantized = codewords[idx] for these 128 rows (float4 coalesced)
    for (int t = tid; t < 128 * (DE / 4); t += 256) {
        int r = t / (DE / 4);
        int q = t % (DE / 4);
        *(float4*)(out_quant + (size_t)(bm + r) * DE + q * 4) =
            *(const float4*)(cw + (size_t)widx[r] * DE + q * 4);
    }
}

// ---------------------------------------------------------------------------
extern "C" void kernel_launch(void* const* d_in, const int* in_sizes, int n_in,
                              void* d_out, int out_size)
{
    (void)in_sizes; (void)n_in; (void)out_size;
    const float* x   = (const float*)d_in[0];
    const float* ew1 = (const float*)d_in[1];
    const float* eb1 = (const float*)d_in[2];
    const float* ew2 = (const float*)d_in[3];
    const float* eb2 = (const float*)d_in[4];
    const float* cw  = (const float*)d_in[5];
    const float* dw1 = (const float*)d_in[6];
    const float* db1 = (const float*)d_in[7];
    const float* dw2 = (const float*)d_in[8];
    const float* db2 = (const float*)d_in[9];

    float* out     = (float*)d_out;
    float* o_idx   = out;                                   // [N]   indices (as f32)
    float* o_dist  = out + NT;                              // [N]   distances
    float* o_rec   = out + 2 * NT;                          // [N, DIN] reconstructed
    float* o_quant = out + 2 * NT + (size_t)NT * DIN;       // [N, DE]  quantized

    float *h, *enc, *gg, *x2, *c2;
    cudaGetSymbolAddress((void**)&h,   g_h);
    cudaGetSymbolAddress((void**)&enc, g_enc);
    cudaGetSymbolAddress((void**)&gg,  g_g);
    cudaGetSymbolAddress((void**)&x2,  g_x2);
    cudaGetSymbolAddress((void**)&c2,  g_c2);

    dim3 blk(256);

    // Encoder
    sgemm_bias<true ><<<dim3(DE  / 128, NT / 128), blk>>>(x,   ew1, eb1, h,   NT, DE,  DIN);
    sgemm_bias<true ><<<dim3(DE  / 128, NT / 128), blk>>>(h,   ew2, eb2, enc, NT, DE,  DE);

    // Norms (c2 independent of encoder; x2 needs enc)
    row_sqnorm<<<KC / 8, dim3(32, 8)>>>(cw,  c2, DE);
    row_sqnorm<<<NT / 8, dim3(32, 8)>>>(enc, x2, DE);

    // Fused VQ distance + argmin + distance + gather
    vq_kernel<<<NT / 128, blk>>>(enc, cw, c2, x2, o_idx, o_dist, o_quant);

    // Decoder
    sgemm_bias<true ><<<dim3(DE  / 128, NT / 128), blk>>>(o_quant, dw1, db1, gg,    NT, DE,  DE);
    sgemm_bias<false><<<dim3(DIN / 128, NT / 128), blk>>>(gg,      dw2, db2, o_rec, NT, DIN, DE);
}

// round 5
// speedup vs baseline: 3.2912x; 3.2912x over previous
#include <cuda_runtime.h>
#include <cuda_bf16.h>
#include <math.h>
#include <stdint.h>

// VQ-VAE forward. Encoder/decoder: scalar fp32 SGEMM (exact path).
// VQ stage: bf16 tensor-core (mma.sync m16n8k16) approximate distance pass
// keeping per-row top-2 candidates, then exact fp32 re-rank of candidates.
#define NT   16384
#define DIN  1024
#define DE   256
#define KC   8192

// ---- scratch (static device arrays; allocation-free) ----------------------
static __device__ float g_h  [(size_t)NT * DE];
static __device__ float g_enc[(size_t)NT * DE];
static __device__ float g_g  [(size_t)NT * DE];
static __device__ float g_x2 [NT];
static __device__ float g_c2 [KC];
static __device__ __align__(16) __nv_bfloat16 g_encb[(size_t)NT * DE];
static __device__ __align__(16) __nv_bfloat16 g_cwb [(size_t)KC * DE];

// ---------------------------------------------------------------------------
// Scalar fp32 SGEMM (R1-proven): C = (opt ReLU)(A @ B + bias)
// ---------------------------------------------------------------------------
template<bool RELU>
__global__ __launch_bounds__(256)
void sgemm_bias(const float* __restrict__ A, const float* __restrict__ B,
                const float* __restrict__ bias, float* __restrict__ C,
                int M, int Nn, int Kk)
{
    const int BM = 128, BN = 128, BK = 16;
    __shared__ float As[BK][BM];
    __shared__ float Bs[BK][BN];

    const int tid = threadIdx.x;
    const int tm  = tid >> 4;
    const int tn  = tid & 15;
    const int bm  = blockIdx.y * BM;
    const int bn  = blockIdx.x * BN;

    float acc[8][8];
#pragma unroll
    for (int i = 0; i < 8; i++)
#pragma unroll
        for (int j = 0; j < 8; j++) acc[i][j] = 0.f;

    for (int k0 = 0; k0 < Kk; k0 += BK) {
#pragma unroll
        for (int i = 0; i < 2; i++) {
            int lin = tid + i * 256;
            int row = lin >> 2;
            int kq  = lin & 3;
            float4 v = *(const float4*)(A + (size_t)(bm + row) * Kk + k0 + kq * 4);
            As[kq * 4 + 0][row] = v.x;
            As[kq * 4 + 1][row] = v.y;
            As[kq * 4 + 2][row] = v.z;
            As[kq * 4 + 3][row] = v.w;
        }
#pragma unroll
        for (int i = 0; i < 2; i++) {
            int lin = tid + i * 256;
            int kr  = lin >> 5;
            int nq  = lin & 31;
            *(float4*)&Bs[kr][nq * 4] =
                *(const float4*)(B + (size_t)(k0 + kr) * Nn + bn + nq * 4);
        }
        __syncthreads();

#pragma unroll
        for (int k = 0; k < BK; k++) {
            float ra[8], rb[8];
#pragma unroll
            for (int i = 0; i < 8; i++) ra[i] = As[k][tm * 8 + i];
#pragma unroll
            for (int j = 0; j < 8; j++) rb[j] = Bs[k][tn * 8 + j];
#pragma unroll
            for (int i = 0; i < 8; i++)
#pragma unroll
                for (int j = 0; j < 8; j++) acc[i][j] += ra[i] * rb[j];
        }
        __syncthreads();
    }

#pragma unroll
    for (int i = 0; i < 8; i++) {
        int row = bm + tm * 8 + i;
#pragma unroll
        for (int j = 0; j < 8; j += 4) {
            int col = bn + tn * 8 + j;
            float4 v;
            v.x = acc[i][j + 0] + bias[col + 0];
            v.y = acc[i][j + 1] + bias[col + 1];
            v.z = acc[i][j + 2] + bias[col + 2];
            v.w = acc[i][j + 3] + bias[col + 3];
            if (RELU) {
                v.x = fmaxf(v.x, 0.f); v.y = fmaxf(v.y, 0.f);
                v.z = fmaxf(v.z, 0.f); v.w = fmaxf(v.w, 0.f);
            }
            *(float4*)(C + (size_t)row * Nn + col) = v;
        }
    }
}

// ---------------------------------------------------------------------------
__global__ void row_sqnorm(const float* __restrict__ X, float* __restrict__ out,
                           int ncols)
{
    int row = blockIdx.x * 8 + threadIdx.y;
    float s = 0.f;
    for (int c = threadIdx.x * 4; c < ncols; c += 128) {
        float4 v = *(const float4*)(X + (size_t)row * ncols + c);
        s += v.x * v.x + v.y * v.y + v.z * v.z + v.w * v.w;
    }
#pragma unroll
    for (int o = 16; o > 0; o >>= 1) s += __shfl_xor_sync(0xFFFFFFFFu, s, o);
    if (threadIdx.x == 0) out[row] = s;
}

// ---------------------------------------------------------------------------
// fp32 -> bf16 with k-permutation inside each 16-block so that mma fragment
// pairs {2tc,2tc+1} and {2tc+8,2tc+9} are adjacent 8-byte groups in smem.
// pos(j) = (j%8)/2*4 + (j/8)*2 + (j%2)
// ---------------------------------------------------------------------------
__global__ void conv_perm(const float* __restrict__ in,
                          __nv_bfloat16* __restrict__ out, int total)
{
    int idx = blockIdx.x * blockDim.x + threadIdx.x;
    if (idx >= total) return;
    int row = idx >> 8, k = idx & 255;
    int blk = k >> 4, j = k & 15;
    int pos = (((j & 7) >> 1) << 2) + ((j >> 3) << 1) + (j & 1);
    out[(row << 8) + (blk << 4) + pos] = __float2bfloat16(in[idx]);
}

// ---------------------------------------------------------------------------
// Tensor-core VQ. Block = 128 rows, loops 64 chunks of 128 codewords.
// 8 warps = 2 (M) x 4 (N); warp tile 64x32 -> full 128x128 coverage.
// smem: enc tile (bf16, 544B-padded rows) + 2x cw chunk buffers (cp.async DB).
// Per-thread top-2 over owned fragment lanes -> smem merge -> exact re-rank.
// ---------------------------------------------------------------------------
#define ROWB 544            // bytes per padded smem row (272 bf16)
#define TILE_B (128 * ROWB) // 69632
#define SMEM_TOTAL (3 * TILE_B)

__device__ __forceinline__ void cpa16(void* dst_smem, const void* src) {
    uint32_t d = (uint32_t)__cvta_generic_to_shared(dst_smem);
    asm volatile("cp.async.cg.shared.global [%0], [%1], 16;\n" :: "r"(d), "l"(src));
}
__device__ __forceinline__ void cpa_commit() {
    asm volatile("cp.async.commit_group;\n");
}
template<int Nw>
__device__ __forceinline__ void cpa_wait() {
    asm volatile("cp.async.wait_group %0;\n" :: "n"(Nw));
}

__device__ __forceinline__ void mma_bf16(float acc[4],
                                         const uint32_t a[4], const uint32_t b[2])
{
    asm volatile(
        "mma.sync.aligned.m16n8k16.row.col.f32.bf16.bf16.f32 "
        "{%0,%1,%2,%3}, {%4,%5,%6,%7}, {%8,%9}, {%0,%1,%2,%3};"
        : "+f"(acc[0]), "+f"(acc[1]), "+f"(acc[2]), "+f"(acc[3])
        : "r"(a[0]), "r"(a[1]), "r"(a[2]), "r"(a[3]), "r"(b[0]), "r"(b[1]));
}

__global__ __launch_bounds__(256, 1)
void vq_bf16(const __nv_bfloat16* __restrict__ encb,
             const __nv_bfloat16* __restrict__ cwb,
             const float* __restrict__ enc,  const float* __restrict__ cw,
             const float* __restrict__ c2,   const float* __restrict__ x2,
             float* __restrict__ out_idx, float* __restrict__ out_dist,
             float* __restrict__ out_quant)
{
    extern __shared__ char smem[];
    char* encS = smem;
    char* cwS[2] = { smem + TILE_B, smem + 2 * TILE_B };

    const int tid   = threadIdx.x;
    const int lane  = tid & 31;
    const int w     = tid >> 5;
    const int warpm = w >> 2;      // 0..1 -> rows warpm*64 .. +63
    const int warpn = w & 3;       // 0..3 -> cols warpn*32 .. +31
    const int gr    = lane >> 2;   // 0..7
    const int tc    = lane & 3;    // 0..3
    const int bm    = blockIdx.x * 128;

    // prefetch chunk 0 (codewords 0..127)
#pragma unroll
    for (int it = 0; it < 16; it++) {
        int lin = tid + it * 256;
        int row = lin >> 5, seg = lin & 31;
        cpa16(cwS[0] + row * ROWB + seg * 16,
              (const char*)cwb + (size_t)row * 512 + seg * 16);
    }
    cpa_commit();

    // load enc tile (plain ld/st, once)
#pragma unroll
    for (int it = 0; it < 16; it++) {
        int lin = tid + it * 256;
        int row = lin >> 5, seg = lin & 31;
        *(uint4*)(encS + row * ROWB + seg * 16) =
            *(const uint4*)((const char*)encb + (size_t)(bm + row) * 512 + seg * 16);
    }

    // per-thread top-2 for 8 row-slots: rs = mt*2 + half
    float m1[8], m2[8];
    int   i1[8], i2[8];
#pragma unroll
    for (int r = 0; r < 8; r++) { m1[r] = 3.4e38f; m2[r] = 3.4e38f; i1[r] = 0; i2[r] = 0; }

    int buf = 0;
    for (int c = 0; c < 64; c++) {
        if (c + 1 < 64) {
#pragma unroll
            for (int it = 0; it < 16; it++) {
                int lin = tid + it * 256;
                int row = lin >> 5, seg = lin & 31;
                cpa16(cwS[buf ^ 1] + row * ROWB + seg * 16,
                      (const char*)cwb + (size_t)((c + 1) * 128 + row) * 512 + seg * 16);
            }
            cpa_commit();
            cpa_wait<1>();
        } else {
            cpa_wait<0>();
        }
        __syncthreads();

        float acc[4][4][4];
#pragma unroll
        for (int mt = 0; mt < 4; mt++)
#pragma unroll
            for (int nt = 0; nt < 4; nt++)
#pragma unroll
                for (int q = 0; q < 4; q++) acc[mt][nt][q] = 0.f;

        const char* cb = cwS[buf];
#pragma unroll 4
        for (int ks = 0; ks < 16; ks++) {
            uint32_t a[4][4], b[4][2];
#pragma unroll
            for (int mt = 0; mt < 4; mt++) {
                const char* base = encS + (warpm * 64 + mt * 16 + gr) * ROWB + ks * 32 + tc * 8;
                uint2 lo = *(const uint2*)base;
                uint2 hi = *(const uint2*)(base + 8 * ROWB);
                a[mt][0] = lo.x; a[mt][2] = lo.y;   // rows gr:   cols 2tc.., 2tc+8..
                a[mt][1] = hi.x; a[mt][3] = hi.y;   // rows gr+8
            }
#pragma unroll
            for (int nt = 0; nt < 4; nt++) {
                const char* base = cb + (warpn * 32 + nt * 8 + gr) * ROWB + ks * 32 + tc * 8;
                uint2 v = *(const uint2*)base;
                b[nt][0] = v.x; b[nt][1] = v.y;
            }
#pragma unroll
            for (int mt = 0; mt < 4; mt++)
#pragma unroll
                for (int nt = 0; nt < 4; nt++) mma_bf16(acc[mt][nt], a[mt], b[nt]);
        }

        // epilogue: d = c2[j] - 2*acc; update per-row-slot top-2
        int cbase = c * 128 + warpn * 32;
#pragma unroll
        for (int nt = 0; nt < 4; nt++) {
            int j0 = cbase + nt * 8 + 2 * tc;
            float2 cc = *(const float2*)(c2 + j0);
#pragma unroll
            for (int mt = 0; mt < 4; mt++) {
#pragma unroll
                for (int half = 0; half < 2; half++) {
                    int rs = mt * 2 + half;
                    float d0 = fmaf(-2.f, acc[mt][nt][half * 2 + 0], cc.x);
                    float d1 = fmaf(-2.f, acc[mt][nt][half * 2 + 1], cc.y);
                    if (d0 < m1[rs]) { m2[rs] = m1[rs]; i2[rs] = i1[rs]; m1[rs] = d0; i1[rs] = j0; }
                    else if (d0 < m2[rs]) { m2[rs] = d0; i2[rs] = j0; }
                    if (d1 < m1[rs]) { m2[rs] = m1[rs]; i2[rs] = i1[rs]; m1[rs] = d1; i1[rs] = j0 + 1; }
                    else if (d1 < m2[rs]) { m2[rs] = d1; i2[rs] = j0 + 1; }
                }
            }
        }
        __syncthreads();
        buf ^= 1;
    }

    // ---- cross-thread merge (reuse cwS[0] region) ----
    float4* ent   = (float4*)cwS[0];           // [128][16] entries, 32 KB
    int2*   cand  = (int2*)(cwS[0] + 32768);   // [128]
    int*    widxS = (int*)(cwS[0] + 32768 + 1024);
    __syncthreads();

#pragma unroll
    for (int mt = 0; mt < 4; mt++)
#pragma unroll
        for (int half = 0; half < 2; half++) {
            int rs = mt * 2 + half;
            int r  = warpm * 64 + mt * 16 + half * 8 + gr;   // 0..127, full coverage
            int slot = warpn * 4 + tc;                        // 0..15
            ent[r * 16 + slot] = make_float4(m1[rs], m2[rs],
                                             __int_as_float(i1[rs]),
                                             __int_as_float(i2[rs]));
        }
    __syncthreads();

    if (tid < 128) {
        float M1 = 3.4e38f, M2 = 3.4e38f;
        int   I1 = 0, I2 = 0;
#pragma unroll
        for (int s = 0; s < 16; s++) {
            float4 e = ent[tid * 16 + s];
            float d; int j;
            d = e.x; j = __float_as_int(e.z);
            if (d < M1 || (d == M1 && j < I1)) { M2 = M1; I2 = I1; M1 = d; I1 = j; }
            else if (d < M2 || (d == M2 && j < I2)) { M2 = d; I2 = j; }
            d = e.y; j = __float_as_int(e.w);
            if (d < M1 || (d == M1 && j < I1)) { M2 = M1; I2 = I1; M1 = d; I1 = j; }
            else if (d < M2 || (d == M2 && j < I2)) { M2 = d; I2 = j; }
        }
        cand[tid] = make_int2(I1, I2);
    }
    __syncthreads();

    // ---- exact fp32 re-rank of the two candidates per row ----
    {
        int rbase = w * 16;
        for (int rr = 0; rr < 16; rr++) {
            int r  = rbase + rr;
            int ia = cand[r].x, ib = cand[r].y;
            const float* er  = enc + (size_t)(bm + r) * DE;
            const float* ca  = cw + (size_t)ia * DE;
            const float* cbp = cw + (size_t)ib * DE;
            float s1 = 0.f, s2 = 0.f;
#pragma unroll
            for (int k = 0; k < 8; k++) {
                float e = er[lane + 32 * k];
                s1 = fmaf(e, ca [lane + 32 * k], s1);
                s2 = fmaf(e, cbp[lane + 32 * k], s2);
            }
#pragma unroll
            for (int o = 16; o > 0; o >>= 1) {
                s1 += __shfl_xor_sync(0xFFFFFFFFu, s1, o);
                s2 += __shfl_xor_sync(0xFFFFFFFFu, s2, o);
            }
            if (lane == 0) {
                float xv = x2[bm + r];
                float da = xv + c2[ia] - 2.f * s1;
                float db = xv + c2[ib] - 2.f * s2;
                int   iw; float dw;
                if (db < da || (db == da && ib < ia)) { iw = ib; dw = db; }
                else                                  { iw = ia; dw = da; }
                out_dist[bm + r] = sqrtf(fmaxf(dw, 0.f));
                out_idx [bm + r] = (float)iw;
                widxS[r] = iw;
            }
        }
    }
    __syncthreads();

    // ---- gather quantized rows (fp32, coalesced) ----
    for (int t = tid; t < 128 * (DE / 4); t += 256) {
        int r = t / (DE / 4);
        int q = t % (DE / 4);
        *(float4*)(out_quant + (size_t)(bm + r) * DE + q * 4) =
            *(const float4*)(cw + (size_t)widxS[r] * DE + q * 4);
    }
}

// ---------------------------------------------------------------------------
extern "C" void kernel_launch(void* const* d_in, const int* in_sizes, int n_in,
                              void* d_out, int out_size)
{
    (void)in_sizes; (void)n_in; (void)out_size;
    const float* x   = (const float*)d_in[0];
    const float* ew1 = (const float*)d_in[1];
    const float* eb1 = (const float*)d_in[2];
    const float* ew2 = (const float*)d_in[3];
    const float* eb2 = (const float*)d_in[4];
    const float* cw  = (const float*)d_in[5];
    const float* dw1 = (const float*)d_in[6];
    const float* db1 = (const float*)d_in[7];
    const float* dw2 = (const float*)d_in[8];
    const float* db2 = (const float*)d_in[9];

    float* out     = (float*)d_out;
    float* o_idx   = out;
    float* o_dist  = out + NT;
    float* o_rec   = out + 2 * NT;
    float* o_quant = out + 2 * NT + (size_t)NT * DIN;

    float *h, *enc, *gg, *x2, *c2;
    __nv_bfloat16 *encb, *cwb;
    cudaGetSymbolAddress((void**)&h,    g_h);
    cudaGetSymbolAddress((void**)&enc,  g_enc);
    cudaGetSymbolAddress((void**)&gg,   g_g);
    cudaGetSymbolAddress((void**)&x2,   g_x2);
    cudaGetSymbolAddress((void**)&c2,   g_c2);
    cudaGetSymbolAddress((void**)&encb, g_encb);
    cudaGetSymbolAddress((void**)&cwb,  g_cwb);

    cudaFuncSetAttribute(vq_bf16, cudaFuncAttributeMaxDynamicSharedMemorySize,
                         SMEM_TOTAL);

    dim3 blk(256);

    // Encoder (exact fp32)
    sgemm_bias<true ><<<dim3(DE / 128, NT / 128), blk>>>(x, ew1, eb1, h,   NT, DE, DIN);
    sgemm_bias<true ><<<dim3(DE / 128, NT / 128), blk>>>(h, ew2, eb2, enc, NT, DE, DE);

    // bf16 permuted copies + norms
    conv_perm<<<(KC * DE) / 256, 256>>>(cw,  cwb,  KC * DE);
    conv_perm<<<(NT * DE) / 256, 256>>>(enc, encb, NT * DE);
    row_sqnorm<<<KC / 8, dim3(32, 8)>>>(cw,  c2, DE);
    row_sqnorm<<<NT / 8, dim3(32, 8)>>>(enc, x2, DE);

    // Tensor-core VQ + exact re-rank + gather
    vq_bf16<<<NT / 128, blk, SMEM_TOTAL>>>(encb, cwb, enc, cw, c2, x2,
                                           o_idx, o_dist, o_quant);

    // Decoder (exact fp32)
    sgemm_bias<true ><<<dim3(DE  / 128, NT / 128), blk>>>(o_quant, dw1, db1, gg, NT, DE, DE);
    sgemm_bias<false><<<dim3(DIN / 128, NT / 128), blk>>>(gg, dw2, db2, o_rec, NT, DIN, DE);
}

// round 6
// speedup vs baseline: 3.2913x; 1.0000x over previous
#include <cuda_runtime.h>
#include <cuda_bf16.h>
#include <math.h>
#include <stdint.h>

// VQ-VAE forward. Encoder/decoder: scalar fp32 SGEMM (exact path).
// VQ stage: bf16 tensor-core (mma.sync m16n8k16) approximate distance pass
// keeping per-row top-2 candidates, then exact fp32 re-rank of candidates.
#define NT   16384
#define DIN  1024
#define DE   256
#define KC   8192

// ---- scratch (static device arrays; allocation-free) ----------------------
static __device__ float g_h  [(size_t)NT * DE];
static __device__ float g_enc[(size_t)NT * DE];
static __device__ float g_g  [(size_t)NT * DE];
static __device__ float g_x2 [NT];
static __device__ float g_c2 [KC];
static __device__ __align__(16) __nv_bfloat16 g_encb[(size_t)NT * DE];
static __device__ __align__(16) __nv_bfloat16 g_cwb [(size_t)KC * DE];

// ---------------------------------------------------------------------------
// Scalar fp32 SGEMM (R1-proven): C = (opt ReLU)(A @ B + bias)
// ---------------------------------------------------------------------------
template<bool RELU>
__global__ __launch_bounds__(256)
void sgemm_bias(const float* __restrict__ A, const float* __restrict__ B,
                const float* __restrict__ bias, float* __restrict__ C,
                int M, int Nn, int Kk)
{
    const int BM = 128, BN = 128, BK = 16;
    __shared__ float As[BK][BM];
    __shared__ float Bs[BK][BN];

    const int tid = threadIdx.x;
    const int tm  = tid >> 4;
    const int tn  = tid & 15;
    const int bm  = blockIdx.y * BM;
    const int bn  = blockIdx.x * BN;

    float acc[8][8];
#pragma unroll
    for (int i = 0; i < 8; i++)
#pragma unroll
        for (int j = 0; j < 8; j++) acc[i][j] = 0.f;

    for (int k0 = 0; k0 < Kk; k0 += BK) {
#pragma unroll
        for (int i = 0; i < 2; i++) {
            int lin = tid + i * 256;
            int row = lin >> 2;
            int kq  = lin & 3;
            float4 v = *(const float4*)(A + (size_t)(bm + row) * Kk + k0 + kq * 4);
            As[kq * 4 + 0][row] = v.x;
            As[kq * 4 + 1][row] = v.y;
            As[kq * 4 + 2][row] = v.z;
            As[kq * 4 + 3][row] = v.w;
        }
#pragma unroll
        for (int i = 0; i < 2; i++) {
            int lin = tid + i * 256;
            int kr  = lin >> 5;
            int nq  = lin & 31;
            *(float4*)&Bs[kr][nq * 4] =
                *(const float4*)(B + (size_t)(k0 + kr) * Nn + bn + nq * 4);
        }
        __syncthreads();

#pragma unroll
        for (int k = 0; k < BK; k++) {
            float ra[8], rb[8];
#pragma unroll
            for (int i = 0; i < 8; i++) ra[i] = As[k][tm * 8 + i];
#pragma unroll
            for (int j = 0; j < 8; j++) rb[j] = Bs[k][tn * 8 + j];
#pragma unroll
            for (int i = 0; i < 8; i++)
#pragma unroll
                for (int j = 0; j < 8; j++) acc[i][j] += ra[i] * rb[j];
        }
        __syncthreads();
    }

#pragma unroll
    for (int i = 0; i < 8; i++) {
        int row = bm + tm * 8 + i;
#pragma unroll
        for (int j = 0; j < 8; j += 4) {
            int col = bn + tn * 8 + j;
            float4 v;
            v.x = acc[i][j + 0] + bias[col + 0];
            v.y = acc[i][j + 1] + bias[col + 1];
            v.z = acc[i][j + 2] + bias[col + 2];
            v.w = acc[i][j + 3] + bias[col + 3];
            if (RELU) {
                v.x = fmaxf(v.x, 0.f); v.y = fmaxf(v.y, 0.f);
                v.z = fmaxf(v.z, 0.f); v.w = fmaxf(v.w, 0.f);
            }
            *(float4*)(C + (size_t)row * Nn + col) = v;
        }
    }
}

// ---------------------------------------------------------------------------
__global__ void row_sqnorm(const float* __restrict__ X, float* __restrict__ out,
                           int ncols)
{
    int row = blockIdx.x * 8 + threadIdx.y;
    float s = 0.f;
    for (int c = threadIdx.x * 4; c < ncols; c += 128) {
        float4 v = *(const float4*)(X + (size_t)row * ncols + c);
        s += v.x * v.x + v.y * v.y + v.z * v.z + v.w * v.w;
    }
#pragma unroll
    for (int o = 16; o > 0; o >>= 1) s += __shfl_xor_sync(0xFFFFFFFFu, s, o);
    if (threadIdx.x == 0) out[row] = s;
}

// ---------------------------------------------------------------------------
// fp32 -> bf16 with k-permutation inside each 16-block so that mma fragment
// pairs {2tc,2tc+1} and {2tc+8,2tc+9} are adjacent 8-byte groups in smem.
// pos(j) = (j%8)/2*4 + (j/8)*2 + (j%2)
// ---------------------------------------------------------------------------
__global__ void conv_perm(const float* __restrict__ in,
                          __nv_bfloat16* __restrict__ out, int total)
{
    int idx = blockIdx.x * blockDim.x + threadIdx.x;
    if (idx >= total) return;
    int row = idx >> 8, k = idx & 255;
    int blk = k >> 4, j = k & 15;
    int pos = (((j & 7) >> 1) << 2) + ((j >> 3) << 1) + (j & 1);
    out[(row << 8) + (blk << 4) + pos] = __float2bfloat16(in[idx]);
}

// ---------------------------------------------------------------------------
// Tensor-core VQ. Block = 128 rows, loops 64 chunks of 128 codewords.
// 8 warps = 2 (M) x 4 (N); warp tile 64x32 -> full 128x128 coverage.
// smem: enc tile (bf16, 544B-padded rows) + 2x cw chunk buffers (cp.async DB).
// Per-thread top-2 over owned fragment lanes -> smem merge -> exact re-rank.
// ---------------------------------------------------------------------------
#define ROWB 544            // bytes per padded smem row (272 bf16)
#define TILE_B (128 * ROWB) // 69632
#define SMEM_TOTAL (3 * TILE_B)

__device__ __forceinline__ void cpa16(void* dst_smem, const void* src) {
    uint32_t d = (uint32_t)__cvta_generic_to_shared(dst_smem);
    asm volatile("cp.async.cg.shared.global [%0], [%1], 16;\n" :: "r"(d), "l"(src));
}
__device__ __forceinline__ void cpa_commit() {
    asm volatile("cp.async.commit_group;\n");
}
template<int Nw>
__device__ __forceinline__ void cpa_wait() {
    asm volatile("cp.async.wait_group %0;\n" :: "n"(Nw));
}

__device__ __forceinline__ void mma_bf16(float acc[4],
                                         const uint32_t a[4], const uint32_t b[2])
{
    asm volatile(
        "mma.sync.aligned.m16n8k16.row.col.f32.bf16.bf16.f32 "
        "{%0,%1,%2,%3}, {%4,%5,%6,%7}, {%8,%9}, {%0,%1,%2,%3};"
        : "+f"(acc[0]), "+f"(acc[1]), "+f"(acc[2]), "+f"(acc[3])
        : "r"(a[0]), "r"(a[1]), "r"(a[2]), "r"(a[3]), "r"(b[0]), "r"(b[1]));
}

__global__ __launch_bounds__(256, 1)
void vq_bf16(const __nv_bfloat16* __restrict__ encb,
             const __nv_bfloat16* __restrict__ cwb,
             const float* __restrict__ enc,  const float* __restrict__ cw,
             const float* __restrict__ c2,   const float* __restrict__ x2,
             float* __restrict__ out_idx, float* __restrict__ out_dist,
             float* __restrict__ out_quant)
{
    extern __shared__ char smem[];
    char* encS = smem;
    char* cwS[2] = { smem + TILE_B, smem + 2 * TILE_B };

    const int tid   = threadIdx.x;
    const int lane  = tid & 31;
    const int w     = tid >> 5;
    const int warpm = w >> 2;      // 0..1 -> rows warpm*64 .. +63
    const int warpn = w & 3;       // 0..3 -> cols warpn*32 .. +31
    const int gr    = lane >> 2;   // 0..7
    const int tc    = lane & 3;    // 0..3
    const int bm    = blockIdx.x * 128;

    // prefetch chunk 0 (codewords 0..127)
#pragma unroll
    for (int it = 0; it < 16; it++) {
        int lin = tid + it * 256;
        int row = lin >> 5, seg = lin & 31;
        cpa16(cwS[0] + row * ROWB + seg * 16,
              (const char*)cwb + (size_t)row * 512 + seg * 16);
    }
    cpa_commit();

    // load enc tile (plain ld/st, once)
#pragma unroll
    for (int it = 0; it < 16; it++) {
        int lin = tid + it * 256;
        int row = lin >> 5, seg = lin & 31;
        *(uint4*)(encS + row * ROWB + seg * 16) =
            *(const uint4*)((const char*)encb + (size_t)(bm + row) * 512 + seg * 16);
    }

    // per-thread top-2 for 8 row-slots: rs = mt*2 + half
    float m1[8], m2[8];
    int   i1[8], i2[8];
#pragma unroll
    for (int r = 0; r < 8; r++) { m1[r] = 3.4e38f; m2[r] = 3.4e38f; i1[r] = 0; i2[r] = 0; }

    int buf = 0;
    for (int c = 0; c < 64; c++) {
        if (c + 1 < 64) {
#pragma unroll
            for (int it = 0; it < 16; it++) {
                int lin = tid + it * 256;
                int row = lin >> 5, seg = lin & 31;
                cpa16(cwS[buf ^ 1] + row * ROWB + seg * 16,
                      (const char*)cwb + (size_t)((c + 1) * 128 + row) * 512 + seg * 16);
            }
            cpa_commit();
            cpa_wait<1>();
        } else {
            cpa_wait<0>();
        }
        __syncthreads();

        float acc[4][4][4];
#pragma unroll
        for (int mt = 0; mt < 4; mt++)
#pragma unroll
            for (int nt = 0; nt < 4; nt++)
#pragma unroll
                for (int q = 0; q < 4; q++) acc[mt][nt][q] = 0.f;

        const char* cb = cwS[buf];
#pragma unroll 4
        for (int ks = 0; ks < 16; ks++) {
            uint32_t a[4][4], b[4][2];
#pragma unroll
            for (int mt = 0; mt < 4; mt++) {
                const char* base = encS + (warpm * 64 + mt * 16 + gr) * ROWB + ks * 32 + tc * 8;
                uint2 lo = *(const uint2*)base;
                uint2 hi = *(const uint2*)(base + 8 * ROWB);
                a[mt][0] = lo.x; a[mt][2] = lo.y;   // rows gr:   cols 2tc.., 2tc+8..
                a[mt][1] = hi.x; a[mt][3] = hi.y;   // rows gr+8
            }
#pragma unroll
            for (int nt = 0; nt < 4; nt++) {
                const char* base = cb + (warpn * 32 + nt * 8 + gr) * ROWB + ks * 32 + tc * 8;
                uint2 v = *(const uint2*)base;
                b[nt][0] = v.x; b[nt][1] = v.y;
            }
#pragma unroll
            for (int mt = 0; mt < 4; mt++)
#pragma unroll
                for (int nt = 0; nt < 4; nt++) mma_bf16(acc[mt][nt], a[mt], b[nt]);
        }

        // epilogue: d = c2[j] - 2*acc; update per-row-slot top-2
        int cbase = c * 128 + warpn * 32;
#pragma unroll
        for (int nt = 0; nt < 4; nt++) {
            int j0 = cbase + nt * 8 + 2 * tc;
            float2 cc = *(const float2*)(c2 + j0);
#pragma unroll
            for (int mt = 0; mt < 4; mt++) {
#pragma unroll
                for (int half = 0; half < 2; half++) {
                    int rs = mt * 2 + half;
                    float d0 = fmaf(-2.f, acc[mt][nt][half * 2 + 0], cc.x);
                    float d1 = fmaf(-2.f, acc[mt][nt][half * 2 + 1], cc.y);
                    if (d0 < m1[rs]) { m2[rs] = m1[rs]; i2[rs] = i1[rs]; m1[rs] = d0; i1[rs] = j0; }
                    else if (d0 < m2[rs]) { m2[rs] = d0; i2[rs] = j0; }
                    if (d1 < m1[rs]) { m2[rs] = m1[rs]; i2[rs] = i1[rs]; m1[rs] = d1; i1[rs] = j0 + 1; }
                    else if (d1 < m2[rs]) { m2[rs] = d1; i2[rs] = j0 + 1; }
                }
            }
        }
        __syncthreads();
        buf ^= 1;
    }

    // ---- cross-thread merge (reuse cwS[0] region) ----
    float4* ent   = (float4*)cwS[0];           // [128][16] entries, 32 KB
    int2*   cand  = (int2*)(cwS[0] + 32768);   // [128]
    int*    widxS = (int*)(cwS[0] + 32768 + 1024);
    __syncthreads();

#pragma unroll
    for (int mt = 0; mt < 4; mt++)
#pragma unroll
        for (int half = 0; half < 2; half++) {
            int rs = mt * 2 + half;
            int r  = warpm * 64 + mt * 16 + half * 8 + gr;   // 0..127, full coverage
            int slot = warpn * 4 + tc;                        // 0..15
            ent[r * 16 + slot] = make_float4(m1[rs], m2[rs],
                                             __int_as_float(i1[rs]),
                                             __int_as_float(i2[rs]));
        }
    __syncthreads();

    if (tid < 128) {
        float M1 = 3.4e38f, M2 = 3.4e38f;
        int   I1 = 0, I2 = 0;
#pragma unroll
        for (int s = 0; s < 16; s++) {
            float4 e = ent[tid * 16 + s];
            float d; int j;
            d = e.x; j = __float_as_int(e.z);
            if (d < M1 || (d == M1 && j < I1)) { M2 = M1; I2 = I1; M1 = d; I1 = j; }
            else if (d < M2 || (d == M2 && j < I2)) { M2 = d; I2 = j; }
            d = e.y; j = __float_as_int(e.w);
            if (d < M1 || (d == M1 && j < I1)) { M2 = M1; I2 = I1; M1 = d; I1 = j; }
            else if (d < M2 || (d == M2 && j < I2)) { M2 = d; I2 = j; }
        }
        cand[tid] = make_int2(I1, I2);
    }
    __syncthreads();

    // ---- exact fp32 re-rank of the two candidates per row ----
    {
        int rbase = w * 16;
        for (int rr = 0; rr < 16; rr++) {
            int r  = rbase + rr;
            int ia = cand[r].x, ib = cand[r].y;
            const float* er  = enc + (size_t)(bm + r) * DE;
            const float* ca  = cw + (size_t)ia * DE;
            const float* cbp = cw + (size_t)ib * DE;
            float s1 = 0.f, s2 = 0.f;
#pragma unroll
            for (int k = 0; k < 8; k++) {
                float e = er[lane + 32 * k];
                s1 = fmaf(e, ca [lane + 32 * k], s1);
                s2 = fmaf(e, cbp[lane + 32 * k], s2);
            }
#pragma unroll
            for (int o = 16; o > 0; o >>= 1) {
                s1 += __shfl_xor_sync(0xFFFFFFFFu, s1, o);
                s2 += __shfl_xor_sync(0xFFFFFFFFu, s2, o);
            }
            if (lane == 0) {
                float xv = x2[bm + r];
                float da = xv + c2[ia] - 2.f * s1;
                float db = xv + c2[ib] - 2.f * s2;
                int   iw; float dw;
                if (db < da || (db == da && ib < ia)) { iw = ib; dw = db; }
                else                                  { iw = ia; dw = da; }
                out_dist[bm + r] = sqrtf(fmaxf(dw, 0.f));
                out_idx [bm + r] = (float)iw;
                widxS[r] = iw;
            }
        }
    }
    __syncthreads();

    // ---- gather quantized rows (fp32, coalesced) ----
    for (int t = tid; t < 128 * (DE / 4); t += 256) {
        int r = t / (DE / 4);
        int q = t % (DE / 4);
        *(float4*)(out_quant + (size_t)(bm + r) * DE + q * 4) =
            *(const float4*)(cw + (size_t)widxS[r] * DE + q * 4);
    }
}

// ---------------------------------------------------------------------------
extern "C" void kernel_launch(void* const* d_in, const int* in_sizes, int n_in,
                              void* d_out, int out_size)
{
    (void)in_sizes; (void)n_in; (void)out_size;
    const float* x   = (const float*)d_in[0];
    const float* ew1 = (const float*)d_in[1];
    const float* eb1 = (const float*)d_in[2];
    const float* ew2 = (const float*)d_in[3];
    const float* eb2 = (const float*)d_in[4];
    const float* cw  = (const float*)d_in[5];
    const float* dw1 = (const float*)d_in[6];
    const float* db1 = (const float*)d_in[7];
    const float* dw2 = (const float*)d_in[8];
    const float* db2 = (const float*)d_in[9];

    float* out     = (float*)d_out;
    float* o_idx   = out;
    float* o_dist  = out + NT;
    float* o_rec   = out + 2 * NT;
    float* o_quant = out + 2 * NT + (size_t)NT * DIN;

    float *h, *enc, *gg, *x2, *c2;
    __nv_bfloat16 *encb, *cwb;
    cudaGetSymbolAddress((void**)&h,    g_h);
    cudaGetSymbolAddress((void**)&enc,  g_enc);
    cudaGetSymbolAddress((void**)&gg,   g_g);
    cudaGetSymbolAddress((void**)&x2,   g_x2);
    cudaGetSymbolAddress((void**)&c2,   g_c2);
    cudaGetSymbolAddress((void**)&encb, g_encb);
    cudaGetSymbolAddress((void**)&cwb,  g_cwb);

    cudaFuncSetAttribute(vq_bf16, cudaFuncAttributeMaxDynamicSharedMemorySize,
                         SMEM_TOTAL);

    dim3 blk(256);

    // Encoder (exact fp32)
    sgemm_bias<true ><<<dim3(DE / 128, NT / 128), blk>>>(x, ew1, eb1, h,   NT, DE, DIN);
    sgemm_bias<true ><<<dim3(DE / 128, NT / 128), blk>>>(h, ew2, eb2, enc, NT, DE, DE);

    // bf16 permuted copies + norms
    conv_perm<<<(KC * DE) / 256, 256>>>(cw,  cwb,  KC * DE);
    conv_perm<<<(NT * DE) / 256, 256>>>(enc, encb, NT * DE);
    row_sqnorm<<<KC / 8, dim3(32, 8)>>>(cw,  c2, DE);
    row_sqnorm<<<NT / 8, dim3(32, 8)>>>(enc, x2, DE);

    // Tensor-core VQ + exact re-rank + gather
    vq_bf16<<<NT / 128, blk, SMEM_TOTAL>>>(encb, cwb, enc, cw, c2, x2,
                                           o_idx, o_dist, o_quant);

    // Decoder (exact fp32)
    sgemm_bias<true ><<<dim3(DE  / 128, NT / 128), blk>>>(o_quant, dw1, db1, gg, NT, DE, DE);
    sgemm_bias<false><<<dim3(DIN / 128, NT / 128), blk>>>(gg, dw2, db2, o_rec, NT, DIN, DE);
}

// round 7
// speedup vs baseline: 3.2917x; 1.0001x over previous
#include <cuda_runtime.h>
#include <cuda_bf16.h>
#include <math.h>
#include <stdint.h>

// VQ-VAE forward. Encoder/decoder: scalar fp32 SGEMM (exact path).
// VQ stage: bf16 tensor-core (mma.sync m16n8k16) approximate distance pass
// keeping per-row top-2 candidates, then exact fp32 re-rank of candidates.
#define NT   16384
#define DIN  1024
#define DE   256
#define KC   8192

// ---- scratch (static device arrays; allocation-free) ----------------------
static __device__ float g_h  [(size_t)NT * DE];
static __device__ float g_enc[(size_t)NT * DE];
static __device__ float g_g  [(size_t)NT * DE];
static __device__ float g_x2 [NT];
static __device__ float g_c2 [KC];
static __device__ __align__(16) __nv_bfloat16 g_encb[(size_t)NT * DE];
static __device__ __align__(16) __nv_bfloat16 g_cwb [(size_t)KC * DE];

// ---------------------------------------------------------------------------
// Scalar fp32 SGEMM (R1-proven): C = (opt ReLU)(A @ B + bias)
// ---------------------------------------------------------------------------
template<bool RELU>
__global__ __launch_bounds__(256)
void sgemm_bias(const float* __restrict__ A, const float* __restrict__ B,
                const float* __restrict__ bias, float* __restrict__ C,
                int M, int Nn, int Kk)
{
    const int BM = 128, BN = 128, BK = 16;
    __shared__ float As[BK][BM];
    __shared__ float Bs[BK][BN];

    const int tid = threadIdx.x;
    const int tm  = tid >> 4;
    const int tn  = tid & 15;
    const int bm  = blockIdx.y * BM;
    const int bn  = blockIdx.x * BN;

    float acc[8][8];
#pragma unroll
    for (int i = 0; i < 8; i++)
#pragma unroll
        for (int j = 0; j < 8; j++) acc[i][j] = 0.f;

    for (int k0 = 0; k0 < Kk; k0 += BK) {
#pragma unroll
        for (int i = 0; i < 2; i++) {
            int lin = tid + i * 256;
            int row = lin >> 2;
            int kq  = lin & 3;
            float4 v = *(const float4*)(A + (size_t)(bm + row) * Kk + k0 + kq * 4);
            As[kq * 4 + 0][row] = v.x;
            As[kq * 4 + 1][row] = v.y;
            As[kq * 4 + 2][row] = v.z;
            As[kq * 4 + 3][row] = v.w;
        }
#pragma unroll
        for (int i = 0; i < 2; i++) {
            int lin = tid + i * 256;
            int kr  = lin >> 5;
            int nq  = lin & 31;
            *(float4*)&Bs[kr][nq * 4] =
                *(const float4*)(B + (size_t)(k0 + kr) * Nn + bn + nq * 4);
        }
        __syncthreads();

#pragma unroll
        for (int k = 0; k < BK; k++) {
            float ra[8], rb[8];
#pragma unroll
            for (int i = 0; i < 8; i++) ra[i] = As[k][tm * 8 + i];
#pragma unroll
            for (int j = 0; j < 8; j++) rb[j] = Bs[k][tn * 8 + j];
#pragma unroll
            for (int i = 0; i < 8; i++)
#pragma unroll
                for (int j = 0; j < 8; j++) acc[i][j] += ra[i] * rb[j];
        }
        __syncthreads();
    }

#pragma unroll
    for (int i = 0; i < 8; i++) {
        int row = bm + tm * 8 + i;
#pragma unroll
        for (int j = 0; j < 8; j += 4) {
            int col = bn + tn * 8 + j;
            float4 v;
            v.x = acc[i][j + 0] + bias[col + 0];
            v.y = acc[i][j + 1] + bias[col + 1];
            v.z = acc[i][j + 2] + bias[col + 2];
            v.w = acc[i][j + 3] + bias[col + 3];
            if (RELU) {
                v.x = fmaxf(v.x, 0.f); v.y = fmaxf(v.y, 0.f);
                v.z = fmaxf(v.z, 0.f); v.w = fmaxf(v.w, 0.f);
            }
            *(float4*)(C + (size_t)row * Nn + col) = v;
        }
    }
}

// ---------------------------------------------------------------------------
__global__ void row_sqnorm(const float* __restrict__ X, float* __restrict__ out,
                           int ncols)
{
    int row = blockIdx.x * 8 + threadIdx.y;
    float s = 0.f;
    for (int c = threadIdx.x * 4; c < ncols; c += 128) {
        float4 v = *(const float4*)(X + (size_t)row * ncols + c);
        s += v.x * v.x + v.y * v.y + v.z * v.z + v.w * v.w;
    }
#pragma unroll
    for (int o = 16; o > 0; o >>= 1) s += __shfl_xor_sync(0xFFFFFFFFu, s, o);
    if (threadIdx.x == 0) out[row] = s;
}

// ---------------------------------------------------------------------------
// fp32 -> bf16 with k-permutation inside each 16-block so that mma fragment
// pairs {2tc,2tc+1} and {2tc+8,2tc+9} are adjacent 8-byte groups in smem.
// pos(j) = (j%8)/2*4 + (j/8)*2 + (j%2)
// ---------------------------------------------------------------------------
__global__ void conv_perm(const float* __restrict__ in,
                          __nv_bfloat16* __restrict__ out, int total)
{
    int idx = blockIdx.x * blockDim.x + threadIdx.x;
    if (idx >= total) return;
    int row = idx >> 8, k = idx & 255;
    int blk = k >> 4, j = k & 15;
    int pos = (((j & 7) >> 1) << 2) + ((j >> 3) << 1) + (j & 1);
    out[(row << 8) + (blk << 4) + pos] = __float2bfloat16(in[idx]);
}

// ---------------------------------------------------------------------------
// Tensor-core VQ. Block = 128 rows, loops 64 chunks of 128 codewords.
// 8 warps = 2 (M) x 4 (N); warp tile 64x32 -> full 128x128 coverage.
// smem: enc tile (bf16, 544B-padded rows) + 2x cw chunk buffers (cp.async DB).
// Per-thread top-2 over owned fragment lanes -> smem merge -> exact re-rank.
// ---------------------------------------------------------------------------
#define ROWB 544            // bytes per padded smem row (272 bf16)
#define TILE_B (128 * ROWB) // 69632
#define SMEM_TOTAL (3 * TILE_B)

__device__ __forceinline__ void cpa16(void* dst_smem, const void* src) {
    uint32_t d = (uint32_t)__cvta_generic_to_shared(dst_smem);
    asm volatile("cp.async.cg.shared.global [%0], [%1], 16;\n" :: "r"(d), "l"(src));
}
__device__ __forceinline__ void cpa_commit() {
    asm volatile("cp.async.commit_group;\n");
}
template<int Nw>
__device__ __forceinline__ void cpa_wait() {
    asm volatile("cp.async.wait_group %0;\n" :: "n"(Nw));
}

__device__ __forceinline__ void mma_bf16(float acc[4],
                                         const uint32_t a[4], const uint32_t b[2])
{
    asm volatile(
        "mma.sync.aligned.m16n8k16.row.col.f32.bf16.bf16.f32 "
        "{%0,%1,%2,%3}, {%4,%5,%6,%7}, {%8,%9}, {%0,%1,%2,%3};"
        : "+f"(acc[0]), "+f"(acc[1]), "+f"(acc[2]), "+f"(acc[3])
        : "r"(a[0]), "r"(a[1]), "r"(a[2]), "r"(a[3]), "r"(b[0]), "r"(b[1]));
}

__global__ __launch_bounds__(256, 1)
void vq_bf16(const __nv_bfloat16* __restrict__ encb,
             const __nv_bfloat16* __restrict__ cwb,
             const float* __restrict__ enc,  const float* __restrict__ cw,
             const float* __restrict__ c2,   const float* __restrict__ x2,
             float* __restrict__ out_idx, float* __restrict__ out_dist,
             float* __restrict__ out_quant)
{
    extern __shared__ char smem[];
    char* encS = smem;
    char* cwS[2] = { smem + TILE_B, smem + 2 * TILE_B };

    const int tid   = threadIdx.x;
    const int lane  = tid & 31;
    const int w     = tid >> 5;
    const int warpm = w >> 2;      // 0..1 -> rows warpm*64 .. +63
    const int warpn = w & 3;       // 0..3 -> cols warpn*32 .. +31
    const int gr    = lane >> 2;   // 0..7
    const int tc    = lane & 3;    // 0..3
    const int bm    = blockIdx.x * 128;

    // prefetch chunk 0 (codewords 0..127)
#pragma unroll
    for (int it = 0; it < 16; it++) {
        int lin = tid + it * 256;
        int row = lin >> 5, seg = lin & 31;
        cpa16(cwS[0] + row * ROWB + seg * 16,
              (const char*)cwb + (size_t)row * 512 + seg * 16);
    }
    cpa_commit();

    // load enc tile (plain ld/st, once)
#pragma unroll
    for (int it = 0; it < 16; it++) {
        int lin = tid + it * 256;
        int row = lin >> 5, seg = lin & 31;
        *(uint4*)(encS + row * ROWB + seg * 16) =
            *(const uint4*)((const char*)encb + (size_t)(bm + row) * 512 + seg * 16);
    }

    // per-thread top-2 for 8 row-slots: rs = mt*2 + half
    float m1[8], m2[8];
    int   i1[8], i2[8];
#pragma unroll
    for (int r = 0; r < 8; r++) { m1[r] = 3.4e38f; m2[r] = 3.4e38f; i1[r] = 0; i2[r] = 0; }

    int buf = 0;
    for (int c = 0; c < 64; c++) {
        if (c + 1 < 64) {
#pragma unroll
            for (int it = 0; it < 16; it++) {
                int lin = tid + it * 256;
                int row = lin >> 5, seg = lin & 31;
                cpa16(cwS[buf ^ 1] + row * ROWB + seg * 16,
                      (const char*)cwb + (size_t)((c + 1) * 128 + row) * 512 + seg * 16);
            }
            cpa_commit();
            cpa_wait<1>();
        } else {
            cpa_wait<0>();
        }
        __syncthreads();

        float acc[4][4][4];
#pragma unroll
        for (int mt = 0; mt < 4; mt++)
#pragma unroll
            for (int nt = 0; nt < 4; nt++)
#pragma unroll
                for (int q = 0; q < 4; q++) acc[mt][nt][q] = 0.f;

        const char* cb = cwS[buf];
#pragma unroll 4
        for (int ks = 0; ks < 16; ks++) {
            uint32_t a[4][4], b[4][2];
#pragma unroll
            for (int mt = 0; mt < 4; mt++) {
                const char* base = encS + (warpm * 64 + mt * 16 + gr) * ROWB + ks * 32 + tc * 8;
                uint2 lo = *(const uint2*)base;
                uint2 hi = *(const uint2*)(base + 8 * ROWB);
                a[mt][0] = lo.x; a[mt][2] = lo.y;   // rows gr:   cols 2tc.., 2tc+8..
                a[mt][1] = hi.x; a[mt][3] = hi.y;   // rows gr+8
            }
#pragma unroll
            for (int nt = 0; nt < 4; nt++) {
                const char* base = cb + (warpn * 32 + nt * 8 + gr) * ROWB + ks * 32 + tc * 8;
                uint2 v = *(const uint2*)base;
                b[nt][0] = v.x; b[nt][1] = v.y;
            }
#pragma unroll
            for (int mt = 0; mt < 4; mt++)
#pragma unroll
                for (int nt = 0; nt < 4; nt++) mma_bf16(acc[mt][nt], a[mt], b[nt]);
        }

        // epilogue: d = c2[j] - 2*acc; update per-row-slot top-2
        int cbase = c * 128 + warpn * 32;
#pragma unroll
        for (int nt = 0; nt < 4; nt++) {
            int j0 = cbase + nt * 8 + 2 * tc;
            float2 cc = *(const float2*)(c2 + j0);
#pragma unroll
            for (int mt = 0; mt < 4; mt++) {
#pragma unroll
                for (int half = 0; half < 2; half++) {
                    int rs = mt * 2 + half;
                    float d0 = fmaf(-2.f, acc[mt][nt][half * 2 + 0], cc.x);
                    float d1 = fmaf(-2.f, acc[mt][nt][half * 2 + 1], cc.y);
                    if (d0 < m1[rs]) { m2[rs] = m1[rs]; i2[rs] = i1[rs]; m1[rs] = d0; i1[rs] = j0; }
                    else if (d0 < m2[rs]) { m2[rs] = d0; i2[rs] = j0; }
                    if (d1 < m1[rs]) { m2[rs] = m1[rs]; i2[rs] = i1[rs]; m1[rs] = d1; i1[rs] = j0 + 1; }
                    else if (d1 < m2[rs]) { m2[rs] = d1; i2[rs] = j0 + 1; }
                }
            }
        }
        __syncthreads();
        buf ^= 1;
    }

    // ---- cross-thread merge (reuse cwS[0] region) ----
    float4* ent   = (float4*)cwS[0];           // [128][16] entries, 32 KB
    int2*   cand  = (int2*)(cwS[0] + 32768);   // [128]
    int*    widxS = (int*)(cwS[0] + 32768 + 1024);
    __syncthreads();

#pragma unroll
    for (int mt = 0; mt < 4; mt++)
#pragma unroll
        for (int half = 0; half < 2; half++) {
            int rs = mt * 2 + half;
            int r  = warpm * 64 + mt * 16 + half * 8 + gr;   // 0..127, full coverage
            int slot = warpn * 4 + tc;                        // 0..15
            ent[r * 16 + slot] = make_float4(m1[rs], m2[rs],
                                             __int_as_float(i1[rs]),
                                             __int_as_float(i2[rs]));
        }
    __syncthreads();

    if (tid < 128) {
        float M1 = 3.4e38f, M2 = 3.4e38f;
        int   I1 = 0, I2 = 0;
#pragma unroll
        for (int s = 0; s < 16; s++) {
            float4 e = ent[tid * 16 + s];
            float d; int j;
            d = e.x; j = __float_as_int(e.z);
            if (d < M1 || (d == M1 && j < I1)) { M2 = M1; I2 = I1; M1 = d; I1 = j; }
            else if (d < M2 || (d == M2 && j < I2)) { M2 = d; I2 = j; }
            d = e.y; j = __float_as_int(e.w);
            if (d < M1 || (d == M1 && j < I1)) { M2 = M1; I2 = I1; M1 = d; I1 = j; }
            else if (d < M2 || (d == M2 && j < I2)) { M2 = d; I2 = j; }
        }
        cand[tid] = make_int2(I1, I2);
    }
    __syncthreads();

    // ---- exact fp32 re-rank of the two candidates per row ----
    {
        int rbase = w * 16;
        for (int rr = 0; rr < 16; rr++) {
            int r  = rbase + rr;
            int ia = cand[r].x, ib = cand[r].y;
            const float* er  = enc + (size_t)(bm + r) * DE;
            const float* ca  = cw + (size_t)ia * DE;
            const float* cbp = cw + (size_t)ib * DE;
            float s1 = 0.f, s2 = 0.f;
#pragma unroll
            for (int k = 0; k < 8; k++) {
                float e = er[lane + 32 * k];
                s1 = fmaf(e, ca [lane + 32 * k], s1);
                s2 = fmaf(e, cbp[lane + 32 * k], s2);
            }
#pragma unroll
            for (int o = 16; o > 0; o >>= 1) {
                s1 += __shfl_xor_sync(0xFFFFFFFFu, s1, o);
                s2 += __shfl_xor_sync(0xFFFFFFFFu, s2, o);
            }
            if (lane == 0) {
                float xv = x2[bm + r];
                float da = xv + c2[ia] - 2.f * s1;
                float db = xv + c2[ib] - 2.f * s2;
                int   iw; float dw;
                if (db < da || (db == da && ib < ia)) { iw = ib; dw = db; }
                else                                  { iw = ia; dw = da; }
                out_dist[bm + r] = sqrtf(fmaxf(dw, 0.f));
                out_idx [bm + r] = (float)iw;
                widxS[r] = iw;
            }
        }
    }
    __syncthreads();

    // ---- gather quantized rows (fp32, coalesced) ----
    for (int t = tid; t < 128 * (DE / 4); t += 256) {
        int r = t / (DE / 4);
        int q = t % (DE / 4);
        *(float4*)(out_quant + (size_t)(bm + r) * DE + q * 4) =
            *(const float4*)(cw + (size_t)widxS[r] * DE + q * 4);
    }
}

// ---------------------------------------------------------------------------
extern "C" void kernel_launch(void* const* d_in, const int* in_sizes, int n_in,
                              void* d_out, int out_size)
{
    (void)in_sizes; (void)n_in; (void)out_size;
    const float* x   = (const float*)d_in[0];
    const float* ew1 = (const float*)d_in[1];
    const float* eb1 = (const float*)d_in[2];
    const float* ew2 = (const float*)d_in[3];
    const float* eb2 = (const float*)d_in[4];
    const float* cw  = (const float*)d_in[5];
    const float* dw1 = (const float*)d_in[6];
    const float* db1 = (const float*)d_in[7];
    const float* dw2 = (const float*)d_in[8];
    const float* db2 = (const float*)d_in[9];

    float* out     = (float*)d_out;
    float* o_idx   = out;
    float* o_dist  = out + NT;
    float* o_rec   = out + 2 * NT;
    float* o_quant = out + 2 * NT + (size_t)NT * DIN;

    float *h, *enc, *gg, *x2, *c2;
    __nv_bfloat16 *encb, *cwb;
    cudaGetSymbolAddress((void**)&h,    g_h);
    cudaGetSymbolAddress((void**)&enc,  g_enc);
    cudaGetSymbolAddress((void**)&gg,   g_g);
    cudaGetSymbolAddress((void**)&x2,   g_x2);
    cudaGetSymbolAddress((void**)&c2,   g_c2);
    cudaGetSymbolAddress((void**)&encb, g_encb);
    cudaGetSymbolAddress((void**)&cwb,  g_cwb);

    cudaFuncSetAttribute(vq_bf16, cudaFuncAttributeMaxDynamicSharedMemorySize,
                         SMEM_TOTAL);

    dim3 blk(256);

    // Encoder (exact fp32)
    sgemm_bias<true ><<<dim3(DE / 128, NT / 128), blk>>>(x, ew1, eb1, h,   NT, DE, DIN);
    sgemm_bias<true ><<<dim3(DE / 128, NT / 128), blk>>>(h, ew2, eb2, enc, NT, DE, DE);

    // bf16 permuted copies + norms
    conv_perm<<<(KC * DE) / 256, 256>>>(cw,  cwb,  KC * DE);
    conv_perm<<<(NT * DE) / 256, 256>>>(enc, encb, NT * DE);
    row_sqnorm<<<KC / 8, dim3(32, 8)>>>(cw,  c2, DE);
    row_sqnorm<<<NT / 8, dim3(32, 8)>>>(enc, x2, DE);

    // Tensor-core VQ + exact re-rank + gather
    vq_bf16<<<NT / 128, blk, SMEM_TOTAL>>>(encb, cwb, enc, cw, c2, x2,
                                           o_idx, o_dist, o_quant);

    // Decoder (exact fp32)
    sgemm_bias<true ><<<dim3(DE  / 128, NT / 128), blk>>>(o_quant, dw1, db1, gg, NT, DE, DE);
    sgemm_bias<false><<<dim3(DIN / 128, NT / 128), blk>>>(gg, dw2, db2, o_rec, NT, DIN, DE);
}